// round 10
// baseline (speedup 1.0000x reference)
#include <cuda_runtime.h>

// Problem constants (fixed by the reference)
#define NN 50000
#define EE 800000
#define DD 64
#define KK 3
#define NSEG (NN * KK)          // 150000
#define SCAN_BS 1024
#define NBLK_SCAN ((NSEG + SCAN_BS - 1) / SCAN_BS)   // 147
#define NSEG_PAD (NBLK_SCAN * SCAN_BS)               // 150528

typedef unsigned long long ull;

// ---------------- scratch (static __device__ arrays; no allocation) ----------
__device__ float g_Ax[NN * DD];
__device__ float g_Dx[NN * DD];
__device__ float g_Bx[KK * NN * DD];
__device__ float g_xnew[NN * DD];
__device__ int   g_cnt[NSEG_PAD];
__device__ int   g_scan[NSEG_PAD];
__device__ int   g_btot[NBLK_SCAN];
__device__ int   g_boff[NBLK_SCAN];
__device__ int   g_start[NSEG];
__device__ int   g_cursor[NSEG];
__device__ int   g_srcs[EE];
__device__ float g_sum[DD];
__device__ float g_sq[DD];

// ---------------- kernel 0: reset per-launch state ---------------------------
__global__ void k_init() {
    int i = blockIdx.x * blockDim.x + threadIdx.x;
    if (i < NSEG_PAD) g_cnt[i] = 0;
    if (i < DD) { g_sum[i] = 0.f; g_sq[i] = 0.f; }
}

// ---------------- f32x2 packed-FMA helpers -----------------------------------
__device__ __forceinline__ void ffma2(ull& d, ull a, ull b) {
    asm("fma.rn.f32x2 %0, %1, %2, %0;" : "+l"(d) : "l"(a), "l"(b));
}
__device__ __forceinline__ ull pack_dup(float x) {
    ull r;
    asm("mov.b64 %0, {%1, %1};" : "=l"(r) : "f"(x));
    return r;
}
__device__ __forceinline__ void unpack2(float& lo, float& hi, ull v) {
    asm("mov.b64 {%0, %1}, %2;" : "=f"(lo), "=f"(hi) : "l"(v));
}
__device__ __forceinline__ float fast_sigmoid(float z) {
    float t;
    asm("tanh.approx.f32 %0, %1;" : "=f"(t) : "f"(0.5f * z));
    return fmaf(0.5f, t, 0.5f);
}

// ---------------- kernel 1: fused 5x GEMM ------------------------------------
// 128 threads/block, 64-node tile. Thread = 4 nodes x 8 features
// (16 ull accumulators = 32 regs -> occupancy, vs R9's 64-acc/255-reg version).
__device__ __forceinline__ void gemm_job(
    float (*__restrict__ xsh)[65], float (*__restrict__ Wsh)[68],
    const float* __restrict__ xg,   // global x base, or nullptr to reuse tile
    const float* __restrict__ W, const float* __restrict__ b,
    float* __restrict__ out, int nb)
{
    int tx = threadIdx.x;            // 0..127
    int pg = tx & 7;                 // feature group: 8*pg .. 8*pg+7
    int ng = tx >> 3;                // node group:    4*ng .. 4*ng+3 (0..15)

    __syncthreads();                 // protect previous job's Wsh/xsh use
    if (xg) {
        #pragma unroll
        for (int it = 0; it < 8; it++) {
            int idx = it * 128 + tx;          // 0..1023 float4 tiles
            int n = idx >> 4, c4 = (idx & 15) * 4;
            int gn = nb + n;
            float4 v = (gn < NN) ? *(const float4*)&xg[gn * DD + c4]
                                 : make_float4(0.f, 0.f, 0.f, 0.f);
            xsh[n][c4]     = v.x;
            xsh[n][c4 + 1] = v.y;
            xsh[n][c4 + 2] = v.z;
            xsh[n][c4 + 3] = v.w;
        }
    }
    #pragma unroll
    for (int it = 0; it < 8; it++) {
        int idx = it * 128 + tx;
        int r = idx >> 4, c4 = (idx & 15) * 4;
        *(float4*)&Wsh[r][c4] = *(const float4*)&W[r * DD + c4];
    }
    __syncthreads();

    ull acc[4][4];
    #pragma unroll
    for (int m = 0; m < 4; m++)
        #pragma unroll
        for (int pp = 0; pp < 4; pp++) acc[m][pp] = 0ull;

    #pragma unroll 8
    for (int d = 0; d < DD; d++) {
        ulonglong2 wa = *(const ulonglong2*)&Wsh[d][8 * pg];      // feats 0..3
        ulonglong2 wb = *(const ulonglong2*)&Wsh[d][8 * pg + 4];  // feats 4..7
        #pragma unroll
        for (int m = 0; m < 4; m++) {
            ull x2 = pack_dup(xsh[ng * 4 + m][d]);
            ffma2(acc[m][0], x2, wa.x);
            ffma2(acc[m][1], x2, wa.y);
            ffma2(acc[m][2], x2, wb.x);
            ffma2(acc[m][3], x2, wb.y);
        }
    }

    float b0 = b[8 * pg],     b1 = b[8 * pg + 1], b2 = b[8 * pg + 2], b3 = b[8 * pg + 3];
    float b4 = b[8 * pg + 4], b5 = b[8 * pg + 5], b6 = b[8 * pg + 6], b7 = b[8 * pg + 7];
    #pragma unroll
    for (int m = 0; m < 4; m++) {
        int n = nb + ng * 4 + m;
        if (n >= NN) continue;
        float v0, v1, v2, v3, v4, v5, v6, v7;
        unpack2(v0, v1, acc[m][0]);
        unpack2(v2, v3, acc[m][1]);
        unpack2(v4, v5, acc[m][2]);
        unpack2(v6, v7, acc[m][3]);
        float4 o0 = make_float4(v0 + b0, v1 + b1, v2 + b2, v3 + b3);
        float4 o1 = make_float4(v4 + b4, v5 + b5, v6 + b6, v7 + b7);
        *(float4*)&out[n * DD + 8 * pg]     = o0;
        *(float4*)&out[n * DD + 8 * pg + 4] = o1;
    }
}

__global__ __launch_bounds__(128) void k_gemm(
    const float* __restrict__ xs,
    const float* __restrict__ Wa, const float* __restrict__ ba,
    const float* __restrict__ Wd, const float* __restrict__ bd,
    const float* __restrict__ Wb, const float* __restrict__ bb)
{
    __shared__ float xsh[64][65];    // 16.6 KB (65: compute reads conflict-free)
    __shared__ float Wsh[64][68];    // 17.4 KB (68: rows 16B-aligned)
    int nb = blockIdx.x * 64;

    const float* x2g = xs + 2 * NN * DD;
    const float* x1g = xs + 1 * NN * DD;
    const float* x0g = xs;

    // Ax, Dx, Bx0 share xs[2]; Bx1 <- xs[1]; Bx2 <- xs[0]
    gemm_job(xsh, Wsh, x2g, Wa,             ba,          g_Ax,             nb);
    gemm_job(xsh, Wsh, 0,   Wd,             bd,          g_Dx,             nb);
    gemm_job(xsh, Wsh, 0,   Wb,             bb,          g_Bx,             nb);
    gemm_job(xsh, Wsh, x1g, Wb +     DD*DD, bb +     DD, g_Bx +     NN*DD, nb);
    gemm_job(xsh, Wsh, x0g, Wb + 2 * DD*DD, bb + 2 * DD, g_Bx + 2 * NN*DD, nb);
}

// ---------------- CSR build: histogram -> scan -> scatter --------------------
__global__ void k_hist(const int* __restrict__ ei, const int* __restrict__ ea) {
    int e = blockIdx.x * blockDim.x + threadIdx.x;
    if (e >= EE) return;
    int seg = ei[EE + e] * KK + (ea[e] - 1);
    atomicAdd(&g_cnt[seg], 1);
}

__global__ __launch_bounds__(SCAN_BS) void k_scanb() {
    __shared__ int sh[SCAN_BS];
    int t = threadIdx.x;
    int i = blockIdx.x * SCAN_BS + t;
    int v = g_cnt[i];
    sh[t] = v;
    __syncthreads();
    for (int o = 1; o < SCAN_BS; o <<= 1) {
        int a = (t >= o) ? sh[t - o] : 0;
        __syncthreads();
        sh[t] += a;
        __syncthreads();
    }
    g_scan[i] = sh[t];
    if (t == SCAN_BS - 1) g_btot[blockIdx.x] = sh[t];
}

__global__ __launch_bounds__(256) void k_scant() {
    __shared__ int sh[256];
    int t = threadIdx.x;
    int v = (t < NBLK_SCAN) ? g_btot[t] : 0;
    sh[t] = v;
    __syncthreads();
    for (int o = 1; o < 256; o <<= 1) {
        int a = (t >= o) ? sh[t - o] : 0;
        __syncthreads();
        sh[t] += a;
        __syncthreads();
    }
    if (t < NBLK_SCAN) g_boff[t] = sh[t] - v;
}

__global__ void k_scana() {
    int i = blockIdx.x * blockDim.x + threadIdx.x;
    if (i >= NSEG) return;
    int ex = g_scan[i] - g_cnt[i] + g_boff[i >> 10];
    g_start[i] = ex;
    g_cursor[i] = ex;
}

__global__ void k_scatter(const int* __restrict__ ei, const int* __restrict__ ea) {
    int e = blockIdx.x * blockDim.x + threadIdx.x;
    if (e >= EE) return;
    int seg = ei[EE + e] * KK + (ea[e] - 1);
    int pos = atomicAdd(&g_cursor[seg], 1);
    g_srcs[pos] = ei[e];
}

// ---------------- segmented gated aggregation (CSR, 4 nodes/block) -----------
__global__ __launch_bounds__(768) void k_agg() {
    int tx   = threadIdx.x;           // feature 0..63
    int slot = threadIdx.y;           // 0..11
    int k    = slot % KK;
    int ln   = slot / KK;             // local node 0..3
    int n    = blockIdx.x * 4 + ln;   // grid = NN/4 -> always < NN

    __shared__ float sh[4][KK][DD];

    float dx = g_Dx[n * DD + tx];
    const float* __restrict__ Bk = g_Bx + k * NN * DD;

    int seg = n * KK + k;
    const int* __restrict__ src = g_srcs + g_start[seg];
    int cnt = g_cnt[seg];

    float num = 0.f, den = 0.f;
    int h = 0;
    for (; h + 4 <= cnt; h += 4) {
        int j0 = src[h], j1 = src[h + 1], j2 = src[h + 2], j3 = src[h + 3];
        float b0 = Bk[j0 * DD + tx];
        float b1 = Bk[j1 * DD + tx];
        float b2 = Bk[j2 * DD + tx];
        float b3 = Bk[j3 * DD + tx];
        float s;
        s = fast_sigmoid(dx + b0); num += s * b0; den += s;
        s = fast_sigmoid(dx + b1); num += s * b1; den += s;
        s = fast_sigmoid(dx + b2); num += s * b2; den += s;
        s = fast_sigmoid(dx + b3); num += s * b3; den += s;
    }
    for (; h < cnt; h++) {
        int j = src[h];
        float b = Bk[j * DD + tx];
        float s = fast_sigmoid(dx + b);
        num += s * b; den += s;
    }
    sh[ln][k][tx] = num / (den + 1e-6f);
    __syncthreads();

    if (slot < 4) {                   // slot as local node id
        int nn = blockIdx.x * 4 + slot;
        float xn = g_Ax[nn * DD + tx]
                 + (1.f / 3.f) * (sh[slot][0][tx] + sh[slot][1][tx] + sh[slot][2][tx]);
        g_xnew[nn * DD + tx] = xn;
    }
}

// ---------------- BN statistics (two-level reduction) ------------------------
__global__ __launch_bounds__(256) void k_stats() {
    int d = threadIdx.x & 63;
    int r = threadIdx.x >> 6;
    float s = 0.f, s2 = 0.f;
    for (int n = blockIdx.x * 4 + r; n < NN; n += gridDim.x * 4) {
        float x = g_xnew[n * DD + d];
        s += x; s2 += x * x;
    }
    __shared__ float sh1[256], sh2[256];
    sh1[threadIdx.x] = s; sh2[threadIdx.x] = s2;
    __syncthreads();
    if (threadIdx.x < 64) {
        float a = sh1[threadIdx.x] + sh1[threadIdx.x + 64]
                + sh1[threadIdx.x + 128] + sh1[threadIdx.x + 192];
        float b = sh2[threadIdx.x] + sh2[threadIdx.x + 64]
                + sh2[threadIdx.x + 128] + sh2[threadIdx.x + 192];
        atomicAdd(&g_sum[d], a);
        atomicAdd(&g_sq[d], b);
    }
}

// ---------------- BatchNorm + ReLU epilogue ----------------------------------
__global__ void k_final(const float* __restrict__ gamma,
                        const float* __restrict__ beta,
                        float* __restrict__ out) {
    int i = blockIdx.x * blockDim.x + threadIdx.x;
    if (i >= NN * DD) return;
    int d = i & 63;
    float mean = g_sum[d] * (1.f / NN);
    float var  = g_sq[d] * (1.f / NN) - mean * mean;   // biased var
    float x = g_xnew[i];
    float y = gamma[d] * (x - mean) * rsqrtf(var + 1e-5f) + beta[d];
    out[i] = fmaxf(y, 0.f);
}

// ---------------- launcher ---------------------------------------------------
// k_gemm kept in the 4th launch slot (the one ncu captures) to verify the
// occupancy fix directly.
extern "C" void kernel_launch(void* const* d_in, const int* in_sizes, int n_in,
                              void* d_out, int out_size) {
    const float* xs    = (const float*)d_in[0];
    const int*   ei    = (const int*)  d_in[1];
    const int*   ea    = (const int*)  d_in[2];
    const float* Wa    = (const float*)d_in[3];
    const float* ba    = (const float*)d_in[4];
    const float* Wd    = (const float*)d_in[5];
    const float* bd    = (const float*)d_in[6];
    const float* Wb    = (const float*)d_in[7];
    const float* bb    = (const float*)d_in[8];
    const float* gamma = (const float*)d_in[9];
    const float* beta  = (const float*)d_in[10];
    float* out = (float*)d_out;

    k_init   <<<(NSEG_PAD + 255) / 256, 256>>>();
    k_hist   <<<(EE + 255) / 256, 256>>>(ei, ea);
    k_scanb  <<<NBLK_SCAN, SCAN_BS>>>();
    k_gemm   <<<(NN + 63) / 64, 128>>>(xs, Wa, ba, Wd, bd, Wb, bb);  // 4th: profiled
    k_scant  <<<1, 256>>>();
    k_scana  <<<(NSEG + 255) / 256, 256>>>();
    k_scatter<<<(EE + 255) / 256, 256>>>(ei, ea);
    k_agg    <<<NN / 4, dim3(64, 12)>>>();
    k_stats  <<<232, 256>>>();
    k_final  <<<(NN * DD + 255) / 256, 256>>>(gamma, beta, out);
}

// round 13
// speedup vs baseline: 1.1450x; 1.1450x over previous
#include <cuda_runtime.h>

// Problem constants (fixed by the reference)
#define NN 50000
#define EE 800000
#define DD 64
#define KK 3
#define NSEG (NN * KK)          // 150000
#define SCAN_BS 1024
#define NBLK_SCAN ((NSEG + SCAN_BS - 1) / SCAN_BS)   // 147
#define NSEG_PAD (NBLK_SCAN * SCAN_BS)               // 150528

typedef unsigned long long ull;

// ---------------- scratch (static __device__ arrays; no allocation) ----------
__device__ float g_Ax[NN * DD];
__device__ float g_Dx[NN * DD];
__device__ float g_Bx[KK * NN * DD];
__device__ float g_xnew[NN * DD];
__device__ int   g_cnt[NSEG_PAD];
__device__ int   g_scan[NSEG_PAD];
__device__ int   g_btot[NBLK_SCAN];
__device__ int   g_boff[NBLK_SCAN];
__device__ int   g_start[NSEG];
__device__ int   g_cursor[NSEG];
__device__ int   g_srcs[EE];
__device__ float g_sum[DD];
__device__ float g_sq[DD];

// ---------------- kernel 0: reset per-launch state ---------------------------
__global__ void k_init() {
    int i = blockIdx.x * blockDim.x + threadIdx.x;
    if (i < NSEG_PAD) g_cnt[i] = 0;
    if (i < DD) { g_sum[i] = 0.f; g_sq[i] = 0.f; }
}

// ---------------- f32x2 packed-FMA helpers -----------------------------------
__device__ __forceinline__ void ffma2(ull& d, ull a, ull b) {
    asm("fma.rn.f32x2 %0, %1, %2, %0;" : "+l"(d) : "l"(a), "l"(b));
}
__device__ __forceinline__ ull pack_dup(float x) {
    ull r;
    asm("mov.b64 %0, {%1, %1};" : "=l"(r) : "f"(x));
    return r;
}
__device__ __forceinline__ void unpack2(float& lo, float& hi, ull v) {
    asm("mov.b64 {%0, %1}, %2;" : "=f"(lo), "=f"(hi) : "l"(v));
}
__device__ __forceinline__ float fast_sigmoid(float z) {
    float t;
    asm("tanh.approx.f32 %0, %1;" : "=f"(t) : "f"(0.5f * z));
    return fmaf(0.5f, t, 0.5f);
}

// ---------------- kernel 1: fused 5x GEMM ------------------------------------
// 128 threads/block, 64-node tile. Thread = 4 nodes x 8 features.
// x staged as float4 over d (1 LDS.128 per node per 4 d-steps). Both smem
// arrays use row stride 68 floats (272 B = 17 x 16 B): EVERY row 16B-aligned
// (R11's stride-65 xsh trapped err715 on odd-row LDS.128). Compute-phase x
// reads are 2-way bank-conflicted (rows m and m+8 share a bank quad) -- 2
// phases for 4 broadcast segments, still ~2x less LDS traffic than scalar x.
__device__ __forceinline__ void gemm_job(
    float (*__restrict__ xsh)[68], float (*__restrict__ Wsh)[68],
    const float* __restrict__ xg,   // global x base, or nullptr to reuse tile
    const float* __restrict__ W, const float* __restrict__ b,
    float* __restrict__ out, int nb)
{
    int tx = threadIdx.x;            // 0..127
    int pg = tx & 7;                 // feature group: 8*pg .. 8*pg+7
    int ng = tx >> 3;                // node group:    4*ng .. 4*ng+3 (0..15)

    __syncthreads();                 // protect previous job's Wsh/xsh use
    if (xg) {
        #pragma unroll
        for (int it = 0; it < 8; it++) {
            int idx = it * 128 + tx;          // 0..1023 float4 tiles
            int n = idx >> 4, c4 = (idx & 15) * 4;
            int gn = nb + n;
            float4 v = (gn < NN) ? *(const float4*)&xg[gn * DD + c4]
                                 : make_float4(0.f, 0.f, 0.f, 0.f);
            *(float4*)&xsh[n][c4] = v;        // aligned: stride 68
        }
    }
    #pragma unroll
    for (int it = 0; it < 8; it++) {
        int idx = it * 128 + tx;
        int r = idx >> 4, c4 = (idx & 15) * 4;
        *(float4*)&Wsh[r][c4] = *(const float4*)&W[r * DD + c4];
    }
    __syncthreads();

    ull acc[4][4];
    #pragma unroll
    for (int m = 0; m < 4; m++)
        #pragma unroll
        for (int pp = 0; pp < 4; pp++) acc[m][pp] = 0ull;

    #pragma unroll 4
    for (int dc = 0; dc < 16; dc++) {         // 4-d chunks
        float xa[4][4];
        #pragma unroll
        for (int m = 0; m < 4; m++)
            *(float4*)xa[m] = *(const float4*)&xsh[ng * 4 + m][dc * 4];
        #pragma unroll
        for (int dd = 0; dd < 4; dd++) {
            int d = dc * 4 + dd;
            ulonglong2 wa = *(const ulonglong2*)&Wsh[d][8 * pg];      // f0..3
            ulonglong2 wb = *(const ulonglong2*)&Wsh[d][8 * pg + 4];  // f4..7
            #pragma unroll
            for (int m = 0; m < 4; m++) {
                ull x2 = pack_dup(xa[m][dd]);
                ffma2(acc[m][0], x2, wa.x);
                ffma2(acc[m][1], x2, wa.y);
                ffma2(acc[m][2], x2, wb.x);
                ffma2(acc[m][3], x2, wb.y);
            }
        }
    }

    float b0 = b[8 * pg],     b1 = b[8 * pg + 1], b2 = b[8 * pg + 2], b3 = b[8 * pg + 3];
    float b4 = b[8 * pg + 4], b5 = b[8 * pg + 5], b6 = b[8 * pg + 6], b7 = b[8 * pg + 7];
    #pragma unroll
    for (int m = 0; m < 4; m++) {
        int n = nb + ng * 4 + m;
        if (n >= NN) continue;
        float v0, v1, v2, v3, v4, v5, v6, v7;
        unpack2(v0, v1, acc[m][0]);
        unpack2(v2, v3, acc[m][1]);
        unpack2(v4, v5, acc[m][2]);
        unpack2(v6, v7, acc[m][3]);
        float4 o0 = make_float4(v0 + b0, v1 + b1, v2 + b2, v3 + b3);
        float4 o1 = make_float4(v4 + b4, v5 + b5, v6 + b6, v7 + b7);
        *(float4*)&out[n * DD + 8 * pg]     = o0;
        *(float4*)&out[n * DD + 8 * pg + 4] = o1;
    }
}

__global__ __launch_bounds__(128) void k_gemm(
    const float* __restrict__ xs,
    const float* __restrict__ Wa, const float* __restrict__ ba,
    const float* __restrict__ Wd, const float* __restrict__ bd,
    const float* __restrict__ Wb, const float* __restrict__ bb)
{
    __shared__ float xsh[64][68];    // 17.4 KB (rows 16B-aligned)
    __shared__ float Wsh[64][68];    // 17.4 KB (rows 16B-aligned)
    int nb = blockIdx.x * 64;

    const float* x2g = xs + 2 * NN * DD;
    const float* x1g = xs + 1 * NN * DD;
    const float* x0g = xs;

    // Ax, Dx, Bx0 share xs[2]; Bx1 <- xs[1]; Bx2 <- xs[0]
    gemm_job(xsh, Wsh, x2g, Wa,             ba,          g_Ax,             nb);
    gemm_job(xsh, Wsh, 0,   Wd,             bd,          g_Dx,             nb);
    gemm_job(xsh, Wsh, 0,   Wb,             bb,          g_Bx,             nb);
    gemm_job(xsh, Wsh, x1g, Wb +     DD*DD, bb +     DD, g_Bx +     NN*DD, nb);
    gemm_job(xsh, Wsh, x0g, Wb + 2 * DD*DD, bb + 2 * DD, g_Bx + 2 * NN*DD, nb);
}

// ---------------- CSR build: histogram -> scan -> scatter --------------------
__global__ void k_hist(const int* __restrict__ ei, const int* __restrict__ ea) {
    int e = blockIdx.x * blockDim.x + threadIdx.x;
    if (e >= EE) return;
    int seg = ei[EE + e] * KK + (ea[e] - 1);
    atomicAdd(&g_cnt[seg], 1);
}

__global__ __launch_bounds__(SCAN_BS) void k_scanb() {
    __shared__ int sh[SCAN_BS];
    int t = threadIdx.x;
    int i = blockIdx.x * SCAN_BS + t;
    int v = g_cnt[i];
    sh[t] = v;
    __syncthreads();
    for (int o = 1; o < SCAN_BS; o <<= 1) {
        int a = (t >= o) ? sh[t - o] : 0;
        __syncthreads();
        sh[t] += a;
        __syncthreads();
    }
    g_scan[i] = sh[t];
    if (t == SCAN_BS - 1) g_btot[blockIdx.x] = sh[t];
}

__global__ __launch_bounds__(256) void k_scant() {
    __shared__ int sh[256];
    int t = threadIdx.x;
    int v = (t < NBLK_SCAN) ? g_btot[t] : 0;
    sh[t] = v;
    __syncthreads();
    for (int o = 1; o < 256; o <<= 1) {
        int a = (t >= o) ? sh[t - o] : 0;
        __syncthreads();
        sh[t] += a;
        __syncthreads();
    }
    if (t < NBLK_SCAN) g_boff[t] = sh[t] - v;
}

__global__ void k_scana() {
    int i = blockIdx.x * blockDim.x + threadIdx.x;
    if (i >= NSEG) return;
    int ex = g_scan[i] - g_cnt[i] + g_boff[i >> 10];
    g_start[i] = ex;
    g_cursor[i] = ex;
}

__global__ void k_scatter(const int* __restrict__ ei, const int* __restrict__ ea) {
    int e = blockIdx.x * blockDim.x + threadIdx.x;
    if (e >= EE) return;
    int seg = ei[EE + e] * KK + (ea[e] - 1);
    int pos = atomicAdd(&g_cursor[seg], 1);
    g_srcs[pos] = ei[e];
}

// ---------------- segmented gated aggregation (CSR, 2 nodes/block) -----------
__global__ __launch_bounds__(384) void k_agg() {
    int tx   = threadIdx.x;           // feature 0..63
    int slot = threadIdx.y;           // 0..5
    int k    = slot % KK;
    int ln   = slot / KK;             // local node 0..1
    int n    = blockIdx.x * 2 + ln;   // NN even -> always < NN

    __shared__ float sh[2][KK][DD];

    float dx = g_Dx[n * DD + tx];
    const float* __restrict__ Bk = g_Bx + k * NN * DD;

    int seg = n * KK + k;
    const int* __restrict__ src = g_srcs + g_start[seg];
    int cnt = g_cnt[seg];

    float num = 0.f, den = 0.f;
    int h = 0;
    for (; h + 4 <= cnt; h += 4) {
        int j0 = src[h], j1 = src[h + 1], j2 = src[h + 2], j3 = src[h + 3];
        float b0 = Bk[j0 * DD + tx];
        float b1 = Bk[j1 * DD + tx];
        float b2 = Bk[j2 * DD + tx];
        float b3 = Bk[j3 * DD + tx];
        float s;
        s = fast_sigmoid(dx + b0); num += s * b0; den += s;
        s = fast_sigmoid(dx + b1); num += s * b1; den += s;
        s = fast_sigmoid(dx + b2); num += s * b2; den += s;
        s = fast_sigmoid(dx + b3); num += s * b3; den += s;
    }
    for (; h < cnt; h++) {
        int j = src[h];
        float b = Bk[j * DD + tx];
        float s = fast_sigmoid(dx + b);
        num += s * b; den += s;
    }
    sh[ln][k][tx] = num / (den + 1e-6f);
    __syncthreads();

    if (slot < 2) {                   // slot as local node id
        int nn = blockIdx.x * 2 + slot;
        float xn = g_Ax[nn * DD + tx]
                 + (1.f / 3.f) * (sh[slot][0][tx] + sh[slot][1][tx] + sh[slot][2][tx]);
        g_xnew[nn * DD + tx] = xn;
    }
}

// ---------------- BN statistics (two-level reduction) ------------------------
__global__ __launch_bounds__(256) void k_stats() {
    int d = threadIdx.x & 63;
    int r = threadIdx.x >> 6;
    float s = 0.f, s2 = 0.f;
    for (int n = blockIdx.x * 4 + r; n < NN; n += gridDim.x * 4) {
        float x = g_xnew[n * DD + d];
        s += x; s2 += x * x;
    }
    __shared__ float sh1[256], sh2[256];
    sh1[threadIdx.x] = s; sh2[threadIdx.x] = s2;
    __syncthreads();
    if (threadIdx.x < 64) {
        float a = sh1[threadIdx.x] + sh1[threadIdx.x + 64]
                + sh1[threadIdx.x + 128] + sh1[threadIdx.x + 192];
        float b = sh2[threadIdx.x] + sh2[threadIdx.x + 64]
                + sh2[threadIdx.x + 128] + sh2[threadIdx.x + 192];
        atomicAdd(&g_sum[d], a);
        atomicAdd(&g_sq[d], b);
    }
}

// ---------------- BatchNorm + ReLU epilogue ----------------------------------
__global__ void k_final(const float* __restrict__ gamma,
                        const float* __restrict__ beta,
                        float* __restrict__ out) {
    int i = blockIdx.x * blockDim.x + threadIdx.x;
    if (i >= NN * DD) return;
    int d = i & 63;
    float mean = g_sum[d] * (1.f / NN);
    float var  = g_sq[d] * (1.f / NN) - mean * mean;   // biased var
    float x = g_xnew[i];
    float y = gamma[d] * (x - mean) * rsqrtf(var + 1e-5f) + beta[d];
    out[i] = fmaxf(y, 0.f);
}

// ---------------- launcher ---------------------------------------------------
// k_gemm kept in the 4th launch slot (the one ncu captures) to verify the
// LDS-traffic fix directly.
extern "C" void kernel_launch(void* const* d_in, const int* in_sizes, int n_in,
                              void* d_out, int out_size) {
    const float* xs    = (const float*)d_in[0];
    const int*   ei    = (const int*)  d_in[1];
    const int*   ea    = (const int*)  d_in[2];
    const float* Wa    = (const float*)d_in[3];
    const float* ba    = (const float*)d_in[4];
    const float* Wd    = (const float*)d_in[5];
    const float* bd    = (const float*)d_in[6];
    const float* Wb    = (const float*)d_in[7];
    const float* bb    = (const float*)d_in[8];
    const float* gamma = (const float*)d_in[9];
    const float* beta  = (const float*)d_in[10];
    float* out = (float*)d_out;

    k_init   <<<(NSEG_PAD + 255) / 256, 256>>>();
    k_hist   <<<(EE + 255) / 256, 256>>>(ei, ea);
    k_scanb  <<<NBLK_SCAN, SCAN_BS>>>();
    k_gemm   <<<(NN + 63) / 64, 128>>>(xs, Wa, ba, Wd, bd, Wb, bb);  // 4th: profiled
    k_scant  <<<1, 256>>>();
    k_scana  <<<(NSEG + 255) / 256, 256>>>();
    k_scatter<<<(EE + 255) / 256, 256>>>(ei, ea);
    k_agg    <<<NN / 2, dim3(64, 6)>>>();
    k_stats  <<<232, 256>>>();
    k_final  <<<(NN * DD + 255) / 256, 256>>>(gamma, beta, out);
}

// round 14
// speedup vs baseline: 1.2583x; 1.0990x over previous
#include <cuda_runtime.h>

// Problem constants (fixed by the reference)
#define NN 50000
#define EE 800000
#define DD 64
#define KK 3
#define NSEG (NN * KK)          // 150000
#define SCAN_BS 1024
#define NBLK_SCAN ((NSEG + SCAN_BS - 1) / SCAN_BS)   // 147
#define NSEG_PAD (NBLK_SCAN * SCAN_BS)               // 150528

typedef unsigned long long ull;

// ---------------- scratch (static __device__ arrays; no allocation) ----------
__device__ float g_Ax[NN * DD];
__device__ float g_Dx[NN * DD];
__device__ float g_Bx[KK * NN * DD];
__device__ float g_xnew[NN * DD];
__device__ int   g_cnt[NSEG_PAD];
__device__ int   g_scan[NSEG_PAD];
__device__ int   g_btot[NBLK_SCAN];
__device__ int   g_boff[NBLK_SCAN];
__device__ int   g_start[NSEG];
__device__ int   g_cursor[NSEG];
__device__ int   g_srcs[EE];
__device__ float g_sum[DD];
__device__ float g_sq[DD];

// ---------------- kernel 0: reset per-launch state ---------------------------
__global__ void k_init() {
    int i = blockIdx.x * blockDim.x + threadIdx.x;
    if (i < NSEG_PAD) g_cnt[i] = 0;
    if (i < DD) { g_sum[i] = 0.f; g_sq[i] = 0.f; }
}

// ---------------- f32x2 packed-FMA helpers -----------------------------------
__device__ __forceinline__ void ffma2(ull& d, ull a, ull b) {
    asm("fma.rn.f32x2 %0, %1, %2, %0;" : "+l"(d) : "l"(a), "l"(b));
}
__device__ __forceinline__ ull pack_dup(float x) {
    ull r;
    asm("mov.b64 %0, {%1, %1};" : "=l"(r) : "f"(x));
    return r;
}
__device__ __forceinline__ void unpack2(float& lo, float& hi, ull v) {
    asm("mov.b64 {%0, %1}, %2;" : "=f"(lo), "=f"(hi) : "l"(v));
}
__device__ __forceinline__ float fast_sigmoid(float z) {
    float t;
    asm("tanh.approx.f32 %0, %1;" : "=f"(t) : "f"(0.5f * z));
    return fmaf(0.5f, t, 0.5f);
}

// ---------------- kernel 1: fused 5x GEMM ------------------------------------
// 64 threads/block, 64-node tile. Thread = 8 nodes x 8 features, node index
// n = m*8 + ng so each warp's simultaneous x reads hit 4 CONSECUTIVE rows
// (bank shifts of 4 -> conflict-free LDS.128; the R13 mapping {m, m+8, ...}
// was an unavoidable 4-way conflict for any 16B-aligned stride).
// Per warp per 4-d chunk: 16 LDS wavefronts vs 128 FFMA2 -> FMA-bound 4:1.
__device__ __forceinline__ void gemm_job(
    float (*__restrict__ xsh)[68], float (*__restrict__ Wsh)[68],
    const float* __restrict__ xg,   // global x base, or nullptr to reuse tile
    const float* __restrict__ W, const float* __restrict__ b,
    float* __restrict__ out, int nb)
{
    int tx = threadIdx.x;            // 0..63
    int pg = tx & 7;                 // feature group: 8*pg .. 8*pg+7
    int ng = tx >> 3;                // 0..7; this thread's nodes: m*8 + ng

    __syncthreads();                 // protect previous job's Wsh/xsh use
    if (xg) {
        #pragma unroll
        for (int it = 0; it < 16; it++) {
            int idx = it * 64 + tx;           // 0..1023 float4 tiles
            int n = idx >> 4, c4 = (idx & 15) * 4;
            int gn = nb + n;
            float4 v = (gn < NN) ? *(const float4*)&xg[gn * DD + c4]
                                 : make_float4(0.f, 0.f, 0.f, 0.f);
            *(float4*)&xsh[n][c4] = v;
        }
    }
    #pragma unroll
    for (int it = 0; it < 16; it++) {
        int idx = it * 64 + tx;
        int r = idx >> 4, c4 = (idx & 15) * 4;
        *(float4*)&Wsh[r][c4] = *(const float4*)&W[r * DD + c4];
    }
    __syncthreads();

    ull acc[8][4];
    #pragma unroll
    for (int m = 0; m < 8; m++)
        #pragma unroll
        for (int pp = 0; pp < 4; pp++) acc[m][pp] = 0ull;

    #pragma unroll 2
    for (int dc = 0; dc < 16; dc++) {         // 4-d chunks
        float xa[8][4];
        #pragma unroll
        for (int m = 0; m < 8; m++)           // rows m*8+ng: warp sees 4
            *(float4*)xa[m] = *(const float4*)&xsh[m * 8 + ng][dc * 4];
        #pragma unroll
        for (int dd = 0; dd < 4; dd++) {
            int d = dc * 4 + dd;
            ulonglong2 wa = *(const ulonglong2*)&Wsh[d][8 * pg];      // f0..3
            ulonglong2 wb = *(const ulonglong2*)&Wsh[d][8 * pg + 4];  // f4..7
            #pragma unroll
            for (int m = 0; m < 8; m++) {
                ull x2 = pack_dup(xa[m][dd]);
                ffma2(acc[m][0], x2, wa.x);
                ffma2(acc[m][1], x2, wa.y);
                ffma2(acc[m][2], x2, wb.x);
                ffma2(acc[m][3], x2, wb.y);
            }
        }
    }

    float4 bl = *(const float4*)&b[8 * pg];
    float4 bh = *(const float4*)&b[8 * pg + 4];
    #pragma unroll
    for (int m = 0; m < 8; m++) {
        int n = nb + m * 8 + ng;
        if (n >= NN) continue;
        float v0, v1, v2, v3, v4, v5, v6, v7;
        unpack2(v0, v1, acc[m][0]);
        unpack2(v2, v3, acc[m][1]);
        unpack2(v4, v5, acc[m][2]);
        unpack2(v6, v7, acc[m][3]);
        float4 o0 = make_float4(v0 + bl.x, v1 + bl.y, v2 + bl.z, v3 + bl.w);
        float4 o1 = make_float4(v4 + bh.x, v5 + bh.y, v6 + bh.z, v7 + bh.w);
        *(float4*)&out[n * DD + 8 * pg]     = o0;
        *(float4*)&out[n * DD + 8 * pg + 4] = o1;
    }
}

__global__ __launch_bounds__(64, 6) void k_gemm(   // reg cap 170: no R9 repeat
    const float* __restrict__ xs,
    const float* __restrict__ Wa, const float* __restrict__ ba,
    const float* __restrict__ Wd, const float* __restrict__ bd,
    const float* __restrict__ Wb, const float* __restrict__ bb)
{
    __shared__ float xsh[64][68];    // 17.4 KB (rows 16B-aligned)
    __shared__ float Wsh[64][68];    // 17.4 KB
    int nb = blockIdx.x * 64;

    const float* x2g = xs + 2 * NN * DD;
    const float* x1g = xs + 1 * NN * DD;
    const float* x0g = xs;

    // Ax, Dx, Bx0 share xs[2]; Bx1 <- xs[1]; Bx2 <- xs[0]
    gemm_job(xsh, Wsh, x2g, Wa,             ba,          g_Ax,             nb);
    gemm_job(xsh, Wsh, 0,   Wd,             bd,          g_Dx,             nb);
    gemm_job(xsh, Wsh, 0,   Wb,             bb,          g_Bx,             nb);
    gemm_job(xsh, Wsh, x1g, Wb +     DD*DD, bb +     DD, g_Bx +     NN*DD, nb);
    gemm_job(xsh, Wsh, x0g, Wb + 2 * DD*DD, bb + 2 * DD, g_Bx + 2 * NN*DD, nb);
}

// ---------------- CSR build: histogram -> scan -> scatter --------------------
__global__ void k_hist(const int* __restrict__ ei, const int* __restrict__ ea) {
    int e = blockIdx.x * blockDim.x + threadIdx.x;
    if (e >= EE) return;
    int seg = ei[EE + e] * KK + (ea[e] - 1);
    atomicAdd(&g_cnt[seg], 1);
}

__global__ __launch_bounds__(SCAN_BS) void k_scanb() {
    __shared__ int sh[SCAN_BS];
    int t = threadIdx.x;
    int i = blockIdx.x * SCAN_BS + t;
    int v = g_cnt[i];
    sh[t] = v;
    __syncthreads();
    for (int o = 1; o < SCAN_BS; o <<= 1) {
        int a = (t >= o) ? sh[t - o] : 0;
        __syncthreads();
        sh[t] += a;
        __syncthreads();
    }
    g_scan[i] = sh[t];
    if (t == SCAN_BS - 1) g_btot[blockIdx.x] = sh[t];
}

__global__ __launch_bounds__(256) void k_scant() {
    __shared__ int sh[256];
    int t = threadIdx.x;
    int v = (t < NBLK_SCAN) ? g_btot[t] : 0;
    sh[t] = v;
    __syncthreads();
    for (int o = 1; o < 256; o <<= 1) {
        int a = (t >= o) ? sh[t - o] : 0;
        __syncthreads();
        sh[t] += a;
        __syncthreads();
    }
    if (t < NBLK_SCAN) g_boff[t] = sh[t] - v;
}

__global__ void k_scana() {
    int i = blockIdx.x * blockDim.x + threadIdx.x;
    if (i >= NSEG) return;
    int ex = g_scan[i] - g_cnt[i] + g_boff[i >> 10];
    g_start[i] = ex;
    g_cursor[i] = ex;
}

__global__ void k_scatter(const int* __restrict__ ei, const int* __restrict__ ea) {
    int e = blockIdx.x * blockDim.x + threadIdx.x;
    if (e >= EE) return;
    int seg = ei[EE + e] * KK + (ea[e] - 1);
    int pos = atomicAdd(&g_cursor[seg], 1);
    g_srcs[pos] = ei[e];
}

// ---------------- segmented gated aggregation (CSR, 2 nodes/block) -----------
__global__ __launch_bounds__(384) void k_agg() {
    int tx   = threadIdx.x;           // feature 0..63
    int slot = threadIdx.y;           // 0..5
    int k    = slot % KK;
    int ln   = slot / KK;             // local node 0..1
    int n    = blockIdx.x * 2 + ln;   // NN even -> always < NN

    __shared__ float sh[2][KK][DD];

    float dx = g_Dx[n * DD + tx];
    const float* __restrict__ Bk = g_Bx + k * NN * DD;

    int seg = n * KK + k;
    const int* __restrict__ src = g_srcs + g_start[seg];
    int cnt = g_cnt[seg];

    float num = 0.f, den = 0.f;
    int h = 0;
    for (; h + 4 <= cnt; h += 4) {
        int j0 = src[h], j1 = src[h + 1], j2 = src[h + 2], j3 = src[h + 3];
        float b0 = Bk[j0 * DD + tx];
        float b1 = Bk[j1 * DD + tx];
        float b2 = Bk[j2 * DD + tx];
        float b3 = Bk[j3 * DD + tx];
        float s;
        s = fast_sigmoid(dx + b0); num += s * b0; den += s;
        s = fast_sigmoid(dx + b1); num += s * b1; den += s;
        s = fast_sigmoid(dx + b2); num += s * b2; den += s;
        s = fast_sigmoid(dx + b3); num += s * b3; den += s;
    }
    for (; h < cnt; h++) {
        int j = src[h];
        float b = Bk[j * DD + tx];
        float s = fast_sigmoid(dx + b);
        num += s * b; den += s;
    }
    sh[ln][k][tx] = num / (den + 1e-6f);
    __syncthreads();

    if (slot < 2) {                   // slot as local node id
        int nn = blockIdx.x * 2 + slot;
        float xn = g_Ax[nn * DD + tx]
                 + (1.f / 3.f) * (sh[slot][0][tx] + sh[slot][1][tx] + sh[slot][2][tx]);
        g_xnew[nn * DD + tx] = xn;
    }
}

// ---------------- BN statistics (two-level reduction) ------------------------
__global__ __launch_bounds__(256) void k_stats() {
    int d = threadIdx.x & 63;
    int r = threadIdx.x >> 6;
    float s = 0.f, s2 = 0.f;
    for (int n = blockIdx.x * 4 + r; n < NN; n += gridDim.x * 4) {
        float x = g_xnew[n * DD + d];
        s += x; s2 += x * x;
    }
    __shared__ float sh1[256], sh2[256];
    sh1[threadIdx.x] = s; sh2[threadIdx.x] = s2;
    __syncthreads();
    if (threadIdx.x < 64) {
        float a = sh1[threadIdx.x] + sh1[threadIdx.x + 64]
                + sh1[threadIdx.x + 128] + sh1[threadIdx.x + 192];
        float b = sh2[threadIdx.x] + sh2[threadIdx.x + 64]
                + sh2[threadIdx.x + 128] + sh2[threadIdx.x + 192];
        atomicAdd(&g_sum[d], a);
        atomicAdd(&g_sq[d], b);
    }
}

// ---------------- BatchNorm + ReLU epilogue ----------------------------------
__global__ void k_final(const float* __restrict__ gamma,
                        const float* __restrict__ beta,
                        float* __restrict__ out) {
    int i = blockIdx.x * blockDim.x + threadIdx.x;
    if (i >= NN * DD) return;
    int d = i & 63;
    float mean = g_sum[d] * (1.f / NN);
    float var  = g_sq[d] * (1.f / NN) - mean * mean;   // biased var
    float x = g_xnew[i];
    float y = gamma[d] * (x - mean) * rsqrtf(var + 1e-5f) + beta[d];
    out[i] = fmaxf(y, 0.f);
}

// ---------------- launcher ---------------------------------------------------
// k_gemm kept in the 4th launch slot (the one ncu captures) to verify the
// conflict-free tile directly.
extern "C" void kernel_launch(void* const* d_in, const int* in_sizes, int n_in,
                              void* d_out, int out_size) {
    const float* xs    = (const float*)d_in[0];
    const int*   ei    = (const int*)  d_in[1];
    const int*   ea    = (const int*)  d_in[2];
    const float* Wa    = (const float*)d_in[3];
    const float* ba    = (const float*)d_in[4];
    const float* Wd    = (const float*)d_in[5];
    const float* bd    = (const float*)d_in[6];
    const float* Wb    = (const float*)d_in[7];
    const float* bb    = (const float*)d_in[8];
    const float* gamma = (const float*)d_in[9];
    const float* beta  = (const float*)d_in[10];
    float* out = (float*)d_out;

    k_init   <<<(NSEG_PAD + 255) / 256, 256>>>();
    k_hist   <<<(EE + 255) / 256, 256>>>(ei, ea);
    k_scanb  <<<NBLK_SCAN, SCAN_BS>>>();
    k_gemm   <<<(NN + 63) / 64, 64>>>(xs, Wa, ba, Wd, bd, Wb, bb);   // 4th: profiled
    k_scant  <<<1, 256>>>();
    k_scana  <<<(NSEG + 255) / 256, 256>>>();
    k_scatter<<<(EE + 255) / 256, 256>>>(ei, ea);
    k_agg    <<<NN / 2, dim3(64, 6)>>>();
    k_stats  <<<232, 256>>>();
    k_final  <<<(NN * DD + 255) / 256, 256>>>(gamma, beta, out);
}